// round 4
// baseline (speedup 1.0000x reference)
#include <cuda_runtime.h>
#include <cstdint>

#define F      1024
#define F4     256
#define DOMS   8
#define NBLK   592          // 4 CTAs/SM x 148 SMs (co-resident; GB300 has 152)
#define TPB    256
#define RMAX   128          // rows per block: ceil(65536/592)=111
#define EPSV   1e-5f

// ---------------- scratch (static device globals; no allocation) ----------------
__device__ int      g_is64;
__device__ unsigned g_ctr1, g_ctr2;
__device__ float    g_psum[(size_t)NBLK * DOMS * F];   // 19.4 MB
__device__ float    g_psq [(size_t)NBLK * DOMS * F];   // 19.4 MB
__device__ int      g_pcnt[NBLK * DOMS];
__device__ float    g_scale[DOMS * F];
__device__ float    g_bias [DOMS * F];

// ---------------- init: zero sync counters + detect y dtype ----------------
__global__ void init_k(const unsigned* __restrict__ yw, int n) {
    if (threadIdx.x == 0) { g_ctr1 = 0u; g_ctr2 = 0u; }
    int lim = min(2048, (n - 1) / 2);   // words in-bounds even if y is int32
    int t = 0;
    for (int i = threadIdx.x; i < lim; i += blockDim.x)
        if (yw[2 * i + 1] != 0u) t = 1; // int64 y in [0,8) -> odd words all zero
    int any = __syncthreads_or(t);
    if (threadIdx.x == 0) g_is64 = any ? 0 : 1;
}

// ---------------- software grid barrier (all NBLK blocks co-resident) ----------------
__device__ __forceinline__ void gsync(unsigned* ctr) {
    __syncthreads();
    if (threadIdx.x == 0) {
        __threadfence();
        atomicAdd(ctr, 1u);
        volatile unsigned* vc = (volatile unsigned*)ctr;
        while (*vc < NBLK) __nanosleep(64);
        __threadfence();
    }
    __syncthreads();
}

// ---------------- fused persistent kernel ----------------
__global__ void __launch_bounds__(TPB, 4) fused_k(
    const float4* __restrict__ x, const void* __restrict__ yv,
    const float* __restrict__ gamma, const float* __restrict__ beta,
    float4* __restrict__ out, int n)
{
    __shared__ int            ysm[RMAX];
    __shared__ unsigned short perm[RMAX];
    __shared__ unsigned char  dsort[RMAX];
    __shared__ int            cnt[DOMS], off[DOMS], scnt[DOMS], cpart[64];
    __shared__ float          sred[18][14], qred[18][14];

    const int tid   = threadIdx.x;
    const int b     = blockIdx.x;
    const int rpb   = (n + NBLK - 1) / NBLK;        // 111 for n=65536
    const int base  = b * rpb;
    const int nrows = min(rpb, n - base);           // may be <=0 for trailing blocks
    const int is64  = g_is64;

    // ================= Phase A: per-block sorted-run partial stats =================
    if (tid < DOMS) cnt[tid] = 0;
    __syncthreads();
    if (tid < nrows) {
        int d = is64 ? (int)((const long long*)yv)[base + tid]
                     : ((const int*)yv)[base + tid];
        ysm[tid] = d;
        atomicAdd(&cnt[d], 1);
    }
    __syncthreads();
    if (tid == 0) {
        int run = 0;
        #pragma unroll
        for (int d = 0; d < DOMS; d++) { off[d] = run; run += cnt[d]; }
    }
    __syncthreads();
    if (tid < nrows) {
        int d = ysm[tid];
        int p = atomicAdd(&off[d], 1);
        perm[p]  = (unsigned short)tid;
        dsort[p] = (unsigned char)d;
    }
    __syncthreads();

    float4* psum = (float4*)(g_psum + (size_t)b * DOMS * F);
    float4* psq  = (float4*)(g_psq  + (size_t)b * DOMS * F);
    const float4* xb = x + (size_t)base * F4 + tid;

    if (nrows > 0) {
        float4 s = make_float4(0.f, 0.f, 0.f, 0.f);
        float4 q = make_float4(0.f, 0.f, 0.f, 0.f);
        int cur = dsort[0];
        int r = 0;
        for (; r + 4 <= nrows; r += 4) {
            float4 v[4]; int dd[4];
            #pragma unroll
            for (int i = 0; i < 4; i++) {
                dd[i] = dsort[r + i];
                v[i]  = xb[(size_t)perm[r + i] * F4];   // default: cache in L2 for phase C
            }
            #pragma unroll
            for (int i = 0; i < 4; i++) {
                if (dd[i] != cur) {                      // warp-uniform (sorted)
                    psum[cur * F4 + tid] = s;
                    psq [cur * F4 + tid] = q;
                    s = make_float4(0.f, 0.f, 0.f, 0.f);
                    q = make_float4(0.f, 0.f, 0.f, 0.f);
                    cur = dd[i];
                }
                s.x += v[i].x; s.y += v[i].y; s.z += v[i].z; s.w += v[i].w;
                q.x = fmaf(v[i].x, v[i].x, q.x);
                q.y = fmaf(v[i].y, v[i].y, q.y);
                q.z = fmaf(v[i].z, v[i].z, q.z);
                q.w = fmaf(v[i].w, v[i].w, q.w);
            }
        }
        for (; r < nrows; r++) {
            int d = dsort[r];
            float4 v = xb[(size_t)perm[r] * F4];
            if (d != cur) {
                psum[cur * F4 + tid] = s;
                psq [cur * F4 + tid] = q;
                s = make_float4(0.f, 0.f, 0.f, 0.f);
                q = make_float4(0.f, 0.f, 0.f, 0.f);
                cur = d;
            }
            s.x += v.x; s.y += v.y; s.z += v.z; s.w += v.w;
            q.x = fmaf(v.x, v.x, q.x); q.y = fmaf(v.y, v.y, q.y);
            q.z = fmaf(v.z, v.z, q.z); q.w = fmaf(v.w, v.w, q.w);
        }
        psum[cur * F4 + tid] = s;
        psq [cur * F4 + tid] = q;
    }
    {
        float4 z = make_float4(0.f, 0.f, 0.f, 0.f);
        #pragma unroll
        for (int d = 0; d < DOMS; d++)
            if (cnt[d] == 0) { psum[d * F4 + tid] = z; psq[d * F4 + tid] = z; }
    }
    if (tid < DOMS) g_pcnt[b * DOMS + tid] = (nrows > 0) ? cnt[tid] : 0;

    gsync(&g_ctr1);

    // ================= Phase B: distributed reduce -> (scale, bias) table =================
    {
        // per-domain total counts: 64 threads (8 dom x 8 slab-groups: 8*74=592)
        if (tid < 64) {
            int d = tid & 7, g = tid >> 3;
            int s0 = g * 74, s1 = min(NBLK, s0 + 74);
            int c = 0;
            for (int s = s0; s < s1; s++) c += g_pcnt[s * DOMS + d];
            cpart[tid] = c;
        }
        __syncthreads();
        if (tid < DOMS) {
            int c = 0;
            #pragma unroll
            for (int g = 0; g < 8; g++) c += cpart[g * 8 + tid];
            scnt[tid] = c;
        }

        // each block owns 14 consecutive (d,f) slots: 592*14 >= 8192
        const int start = b * 14;
        const int p = tid % 14, c = tid / 14;       // c in 0..18 (c==18 idle)
        if (c < 18 && start + p < DOMS * F) {
            int j  = start + p;
            int s0 = c * 33, s1 = min(NBLK, s0 + 33);   // 18*33 = 594 >= 592
            float s = 0.f, q = 0.f;
            for (int sl = s0; sl < s1; sl++) {
                s += g_psum[(size_t)sl * (DOMS * F) + j];
                q += g_psq [(size_t)sl * (DOMS * F) + j];
            }
            sred[c][p] = s; qred[c][p] = q;
        }
        __syncthreads();
        if (tid < 14 && start + tid < DOMS * F) {
            int jj = start + tid;
            float s = 0.f, q = 0.f;
            #pragma unroll
            for (int cc = 0; cc < 18; cc++) { s += sred[cc][tid]; q += qred[cc][tid]; }
            int d = jj >> 10, f = jj & (F - 1);
            float cf = (float)scnt[d];
            float sc, bi;
            if (cf > 1.f) {
                float inv  = 1.f / cf;
                float mean = s * inv;
                float var  = fmaxf(q * inv - mean * mean, 0.f);
                sc = gamma[f] * rsqrtf(var + EPSV);
                bi = fmaf(-mean, sc, beta[f]);
            } else if (cf == 1.f) { sc = 1.f; bi = 0.f; }   // count==1 -> raw x
            else                  { sc = 0.f; bi = 0.f; }   // count==0 -> 0
            g_scale[jj] = sc;
            g_bias [jj] = bi;
        }
    }

    gsync(&g_ctr2);

    // ================= Phase C: normalize own chunk, reverse of phase-A read order =================
    // LRU replay of this block's x lines in L2; (scale,bias) register-cached per domain run.
    if (nrows > 0) {
        const float4* sc4 = (const float4*)g_scale;
        const float4* bi4 = (const float4*)g_bias;
        const float4* xc  = x   + (size_t)base * F4 + tid;
        float4*       oc  = out + (size_t)base * F4 + tid;

        int cur = dsort[nrows - 1];
        float4 sc = sc4[cur * F4 + tid];
        float4 bi = bi4[cur * F4 + tid];

        int r = nrows - 1;
        for (; r - 3 >= 0; r -= 4) {
            float4 v[4]; int row[4];
            #pragma unroll
            for (int i = 0; i < 4; i++) {
                row[i] = perm[r - i];
                v[i]   = __ldcs(xc + (size_t)row[i] * F4);
            }
            #pragma unroll
            for (int i = 0; i < 4; i++) {
                int d = dsort[r - i];
                if (d != cur) {                          // warp-uniform, rare (<=8 total)
                    cur = d;
                    sc = sc4[cur * F4 + tid];
                    bi = bi4[cur * F4 + tid];
                }
                float4 o;
                o.x = fmaf(v[i].x, sc.x, bi.x);
                o.y = fmaf(v[i].y, sc.y, bi.y);
                o.z = fmaf(v[i].z, sc.z, bi.z);
                o.w = fmaf(v[i].w, sc.w, bi.w);
                __stcs(oc + (size_t)row[i] * F4, o);
            }
        }
        for (; r >= 0; r--) {
            int row = perm[r];
            int d   = dsort[r];
            if (d != cur) {
                cur = d;
                sc = sc4[cur * F4 + tid];
                bi = bi4[cur * F4 + tid];
            }
            float4 v = __ldcs(xc + (size_t)row * F4);
            float4 o;
            o.x = fmaf(v.x, sc.x, bi.x);
            o.y = fmaf(v.y, sc.y, bi.y);
            o.z = fmaf(v.z, sc.z, bi.z);
            o.w = fmaf(v.w, sc.w, bi.w);
            __stcs(oc + (size_t)row * F4, o);
        }
    }
}

// ---------------- launch ----------------
extern "C" void kernel_launch(void* const* d_in, const int* in_sizes, int n_in,
                              void* d_out, int out_size) {
    const float4* x     = (const float4*)d_in[0];
    const void*   y     = d_in[1];
    const float*  gamma = (const float*)d_in[2];
    const float*  beta  = (const float*)d_in[3];
    float4*       out   = (float4*)d_out;

    int n = in_sizes[1];   // batch (y element count)

    init_k <<<1, 256>>>((const unsigned*)y, n);
    fused_k<<<NBLK, TPB>>>(x, y, gamma, beta, out, n);
}

// round 5
// speedup vs baseline: 1.0136x; 1.0136x over previous
#include <cuda_runtime.h>
#include <cstdint>

#define F      1024
#define F4     256
#define DOMS   8
#define NBLK   296          // 2 CTAs/SM x 148 SMs (co-resident; GB300 has 152)
#define TPB    256
#define RMAX   256          // rows per block: ceil(65536/296)=222
#define EPSV   1e-5f

// ---------------- scratch (static device globals; no allocation) ----------------
__device__ unsigned g_count = 0, g_gen = 0;            // generation barrier state
__device__ float    g_psum[(size_t)NBLK * DOMS * F];   // 9.7 MB
__device__ float    g_psq [(size_t)NBLK * DOMS * F];   // 9.7 MB
__device__ int      g_pcnt[NBLK * DOMS];
__device__ float    g_scale[DOMS * F];
__device__ float    g_bias [DOMS * F];

// ---------------- generation-based grid barrier (no per-launch reset needed) ----------------
__device__ __forceinline__ void gsync() {
    __syncthreads();
    if (threadIdx.x == 0) {
        unsigned my = *(volatile unsigned*)&g_gen;
        __threadfence();
        unsigned old = atomicAdd(&g_count, 1u);
        if (old == NBLK - 1) {
            g_count = 0;                 // safe: all arrived, none past gen flip yet
            __threadfence();
            atomicAdd(&g_gen, 1u);
        } else {
            while (*(volatile unsigned*)&g_gen == my) __nanosleep(32);
        }
        __threadfence();
    }
    __syncthreads();
}

// ---------------- fused persistent kernel ----------------
__global__ void __launch_bounds__(TPB, 2) fused_k(
    const float4* __restrict__ x, const void* __restrict__ yv,
    const float* __restrict__ gamma, const float* __restrict__ beta,
    float4* __restrict__ out, int n)
{
    __shared__ int            ysm[RMAX];
    __shared__ unsigned short perm[RMAX];
    __shared__ unsigned char  dsort[RMAX];
    __shared__ int            cnt[DOMS], off[DOMS], scnt[DOMS], cpart[64];
    __shared__ float          sred[9][28], qred[9][28];

    const int tid   = threadIdx.x;
    const int b     = blockIdx.x;
    const int rpb   = (n + NBLK - 1) / NBLK;        // 222 for n=65536
    const int base  = b * rpb;
    const int nrows = min(rpb, n - base);

    // ---- in-block y dtype detection (int64 vs int32); words [0, n) only ----
    // int64 y in [0,8): every odd 32-bit word is 0. int32: P(all zero) = 8^-1024.
    int is64;
    {
        const unsigned* yw = (const unsigned*)yv;
        int lim = min(1024, (n - 1) / 2);           // pairs; odd index 2i+1 < n
        int t = 0;
        for (int i = tid; i < lim; i += TPB)
            if (yw[2 * i + 1] != 0u) t = 1;
        is64 = __syncthreads_or(t) ? 0 : 1;
    }

    // ================= Phase A: per-block sorted-run partial stats =================
    if (tid < DOMS) cnt[tid] = 0;
    __syncthreads();
    if (tid < nrows) {
        int d = is64 ? (int)((const long long*)yv)[base + tid]
                     : ((const int*)yv)[base + tid];
        ysm[tid] = d;
        atomicAdd(&cnt[d], 1);
    }
    __syncthreads();
    if (tid == 0) {
        int run = 0;
        #pragma unroll
        for (int d = 0; d < DOMS; d++) { off[d] = run; run += cnt[d]; }
    }
    __syncthreads();
    if (tid < nrows) {
        int d = ysm[tid];
        int p = atomicAdd(&off[d], 1);
        perm[p]  = (unsigned short)tid;
        dsort[p] = (unsigned char)d;
    }
    __syncthreads();

    float4* psum = (float4*)(g_psum + (size_t)b * DOMS * F);
    float4* psq  = (float4*)(g_psq  + (size_t)b * DOMS * F);
    const float4* xb = x + (size_t)base * F4 + tid;

    if (nrows > 0) {
        float4 s = make_float4(0.f, 0.f, 0.f, 0.f);
        float4 q = make_float4(0.f, 0.f, 0.f, 0.f);
        int cur = dsort[0];
        int r = 0;
        for (; r + 8 <= nrows; r += 8) {
            float4 v[8]; int dd[8];
            #pragma unroll
            for (int i = 0; i < 8; i++) {
                dd[i] = dsort[r + i];
                v[i]  = xb[(size_t)perm[r + i] * F4];   // default: stays in L2 for phase C
            }
            #pragma unroll
            for (int i = 0; i < 8; i++) {
                if (dd[i] != cur) {                      // warp-uniform (sorted)
                    psum[cur * F4 + tid] = s;
                    psq [cur * F4 + tid] = q;
                    s = make_float4(0.f, 0.f, 0.f, 0.f);
                    q = make_float4(0.f, 0.f, 0.f, 0.f);
                    cur = dd[i];
                }
                s.x += v[i].x; s.y += v[i].y; s.z += v[i].z; s.w += v[i].w;
                q.x = fmaf(v[i].x, v[i].x, q.x);
                q.y = fmaf(v[i].y, v[i].y, q.y);
                q.z = fmaf(v[i].z, v[i].z, q.z);
                q.w = fmaf(v[i].w, v[i].w, q.w);
            }
        }
        for (; r < nrows; r++) {
            int d = dsort[r];
            float4 v = xb[(size_t)perm[r] * F4];
            if (d != cur) {
                psum[cur * F4 + tid] = s;
                psq [cur * F4 + tid] = q;
                s = make_float4(0.f, 0.f, 0.f, 0.f);
                q = make_float4(0.f, 0.f, 0.f, 0.f);
                cur = d;
            }
            s.x += v.x; s.y += v.y; s.z += v.z; s.w += v.w;
            q.x = fmaf(v.x, v.x, q.x); q.y = fmaf(v.y, v.y, q.y);
            q.z = fmaf(v.z, v.z, q.z); q.w = fmaf(v.w, v.w, q.w);
        }
        psum[cur * F4 + tid] = s;
        psq [cur * F4 + tid] = q;
    }
    {
        float4 z = make_float4(0.f, 0.f, 0.f, 0.f);
        #pragma unroll
        for (int d = 0; d < DOMS; d++)
            if (cnt[d] == 0) { psum[d * F4 + tid] = z; psq[d * F4 + tid] = z; }
    }
    if (tid < DOMS) g_pcnt[b * DOMS + tid] = (nrows > 0) ? cnt[tid] : 0;

    gsync();

    // ================= Phase B: distributed reduce -> (scale, bias) table =================
    {
        // per-domain total counts: 64 threads (8 dom x 8 slab-groups: 8*37=296)
        if (tid < 64) {
            int d = tid & 7, g = tid >> 3;
            int s0 = g * 37, s1 = min(NBLK, s0 + 37);
            int c = 0;
            for (int s = s0; s < s1; s++) c += g_pcnt[s * DOMS + d];
            cpart[tid] = c;
        }
        __syncthreads();
        if (tid < DOMS) {
            int c = 0;
            #pragma unroll
            for (int g = 0; g < 8; g++) c += cpart[g * 8 + tid];
            scnt[tid] = c;
        }

        // each block owns 28 consecutive (d,f) slots: 296*28 >= 8192
        const int start = b * 28;
        const int p = tid % 28, c = tid / 28;       // c in 0..9 (c==9 idle)
        if (c < 9 && start + p < DOMS * F) {
            int j  = start + p;
            int s0 = c * 33, s1 = min(NBLK, s0 + 33);   // 9*33 = 297 >= 296
            float s = 0.f, q = 0.f;
            for (int sl = s0; sl < s1; sl++) {
                s += g_psum[(size_t)sl * (DOMS * F) + j];
                q += g_psq [(size_t)sl * (DOMS * F) + j];
            }
            sred[c][p] = s; qred[c][p] = q;
        }
        __syncthreads();
        if (tid < 28 && start + tid < DOMS * F) {
            int jj = start + tid;
            float s = 0.f, q = 0.f;
            #pragma unroll
            for (int cc = 0; cc < 9; cc++) { s += sred[cc][tid]; q += qred[cc][tid]; }
            int d = jj >> 10, f = jj & (F - 1);
            float cf = (float)scnt[d];
            float sc, bi;
            if (cf > 1.f) {
                float inv  = 1.f / cf;
                float mean = s * inv;
                float var  = fmaxf(q * inv - mean * mean, 0.f);
                sc = gamma[f] * rsqrtf(var + EPSV);
                bi = fmaf(-mean, sc, beta[f]);
            } else if (cf == 1.f) { sc = 1.f; bi = 0.f; }   // count==1 -> raw x
            else                  { sc = 0.f; bi = 0.f; }   // count==0 -> 0
            g_scale[jj] = sc;
            g_bias [jj] = bi;
        }
    }

    gsync();

    // ================= Phase C: normalize own chunk, reverse of phase-A read order =================
    // LRU replay of this block's x lines in L2; (scale,bias) register-cached per domain run.
    if (nrows > 0) {
        const float4* sc4 = (const float4*)g_scale;
        const float4* bi4 = (const float4*)g_bias;
        const float4* xc  = x   + (size_t)base * F4 + tid;
        float4*       oc  = out + (size_t)base * F4 + tid;

        int cur = dsort[nrows - 1];
        float4 sc = sc4[cur * F4 + tid];
        float4 bi = bi4[cur * F4 + tid];

        int r = nrows - 1;
        for (; r - 7 >= 0; r -= 8) {
            float4 v[8]; int row[8];
            #pragma unroll
            for (int i = 0; i < 8; i++) {
                row[i] = perm[r - i];
                v[i]   = __ldcs(xc + (size_t)row[i] * F4);
            }
            #pragma unroll
            for (int i = 0; i < 8; i++) {
                int d = dsort[r - i];
                if (d != cur) {                          // warp-uniform, rare (<=8 total)
                    cur = d;
                    sc = sc4[cur * F4 + tid];
                    bi = bi4[cur * F4 + tid];
                }
                float4 o;
                o.x = fmaf(v[i].x, sc.x, bi.x);
                o.y = fmaf(v[i].y, sc.y, bi.y);
                o.z = fmaf(v[i].z, sc.z, bi.z);
                o.w = fmaf(v[i].w, sc.w, bi.w);
                __stcs(oc + (size_t)row[i] * F4, o);
            }
        }
        for (; r >= 0; r--) {
            int row = perm[r];
            int d   = dsort[r];
            if (d != cur) {
                cur = d;
                sc = sc4[cur * F4 + tid];
                bi = bi4[cur * F4 + tid];
            }
            float4 v = __ldcs(xc + (size_t)row * F4);
            float4 o;
            o.x = fmaf(v.x, sc.x, bi.x);
            o.y = fmaf(v.y, sc.y, bi.y);
            o.z = fmaf(v.z, sc.z, bi.z);
            o.w = fmaf(v.w, sc.w, bi.w);
            __stcs(oc + (size_t)row * F4, o);
        }
    }
}

// ---------------- launch ----------------
extern "C" void kernel_launch(void* const* d_in, const int* in_sizes, int n_in,
                              void* d_out, int out_size) {
    const float4* x     = (const float4*)d_in[0];
    const void*   y     = d_in[1];
    const float*  gamma = (const float*)d_in[2];
    const float*  beta  = (const float*)d_in[3];
    float4*       out   = (float4*)d_out;

    int n = in_sizes[1];   // batch (y element count)

    fused_k<<<NBLK, TPB>>>(x, y, gamma, beta, out, n);
}